// round 2
// baseline (speedup 1.0000x reference)
#include <cuda_runtime.h>
#include <cstdint>
#include <math.h>

// ----------------------------------------------------------------------------
// Problem constants
//   B=16, Nf=1024, Nh=1024, Ng=2048, H=256, L=4 (2 encoders x 2 sublayers)
// ----------------------------------------------------------------------------
#define HDIM 256

// ----------------------------------------------------------------------------
// Scratch (device globals — allocation-free rule)
// ----------------------------------------------------------------------------
__device__ float g_t0  [16 * 2048 * 256];      // proj ping
__device__ float g_t1  [16 * 2048 * 256];      // proj pong
__device__ float g_q   [16 * 1024 * 256];
__device__ float g_k   [16 * 2048 * 256];
__device__ float g_v   [16 * 2048 * 256];
__device__ float g_s   [16L * 1024 * 2048];    // scores / weights (128 MB)
__device__ float g_attn[16 * 1024 * 256];
__device__ float g_xA  [16 * 1024 * 256];
__device__ float g_xB  [16 * 1024 * 256];
__device__ int   g_mtype_hf;                   // 0=int32, 1=uint8, 2=float32
__device__ int   g_mtype_fg;

// ----------------------------------------------------------------------------
// Mask dtype detection. The reference produces bool masks; the harness promotes
// them to an unknown concrete dtype. Classify on-device (deterministic,
// graph-capturable):
//   int32  -> every 4-byte word is 0 or 1
//   uint8  -> every byte is 0 or 1, but some packed word > 1
//   float32-> words are 0 or 0x3f800000
// Scan the first n_words (safe for all encodings: n_words <= n_elems/4).
// ----------------------------------------------------------------------------
__global__ void detect_mask_kernel(const uint32_t* __restrict__ m,
                                   int n_words, int* __restrict__ flag_out)
{
    __shared__ int word_gt1;     // some word not in {0,1}
    __shared__ int byte_bad;     // some byte not in {0,1}
    if (threadIdx.x == 0) { word_gt1 = 0; byte_bad = 0; }
    __syncthreads();

    int lw = 0, lb = 0;
    for (int i = threadIdx.x; i < n_words; i += blockDim.x) {
        uint32_t w = m[i];
        if (w > 1u) lw = 1;
        #pragma unroll
        for (int b = 0; b < 4; b++) {
            uint32_t byte = (w >> (8 * b)) & 0xFFu;
            if (byte > 1u) lb = 1;
        }
    }
    if (lw) atomicOr(&word_gt1, 1);
    if (lb) atomicOr(&byte_bad, 1);
    __syncthreads();

    if (threadIdx.x == 0) {
        int t;
        if (!word_gt1)      t = 0;   // int32
        else if (!byte_bad) t = 1;   // uint8 (packed bools)
        else                t = 2;   // float32
        *flag_out = t;
    }
}

// ----------------------------------------------------------------------------
// SGEMM: C = alpha * A @ B (+ bias), optional B transposed (A @ B^T).
//   A: [M,K] row-major.  B: NN -> [K,N], NT -> [N,K].  batch via blockIdx.z.
//   Tiles: BM=64, BN=64, BK=32, 128 threads, 8x4 per-thread microtile.
//   All dims used here are multiples of the tile sizes -> no bounds checks.
// ----------------------------------------------------------------------------
template<bool TRANS_B, bool BIAS>
__global__ __launch_bounds__(128)
void sgemm_kernel(const float* __restrict__ A,
                  const float* __restrict__ B,
                  const float* __restrict__ bias,
                  float* __restrict__ C,
                  int M, int N, int K,
                  long long sA, long long sB, long long sC,
                  float alpha)
{
    constexpr int BM = 64, BN = 64, BK = 32;
    __shared__ float As[BK][BM];
    __shared__ float Bs[BK][BN];

    const int bz = blockIdx.z;
    A += (long long)bz * sA;
    B += (long long)bz * sB;
    C += (long long)bz * sC;

    const int m0 = blockIdx.y * BM;
    const int n0 = blockIdx.x * BN;
    const int tid = threadIdx.x;          // 0..127
    const int ty = tid >> 4;              // 0..7  -> 8 rows of threads
    const int tx = tid & 15;              // 0..15 -> 16 cols of threads

    float acc[8][4];
    #pragma unroll
    for (int i = 0; i < 8; i++)
        #pragma unroll
        for (int j = 0; j < 4; j++) acc[i][j] = 0.f;

    for (int k0 = 0; k0 < K; k0 += BK) {
        // ---- load A tile (64x32) transposed into As[k][m] ----
        #pragma unroll
        for (int i = 0; i < 4; i++) {
            int id  = tid + i * 128;          // 0..511
            int row = id >> 3;                // 0..63
            int kv  = id & 7;                 // 0..7 (float4 along k)
            float4 va = *(const float4*)(A + (long long)(m0 + row) * K + k0 + kv * 4);
            As[kv * 4 + 0][row] = va.x;
            As[kv * 4 + 1][row] = va.y;
            As[kv * 4 + 2][row] = va.z;
            As[kv * 4 + 3][row] = va.w;
        }
        // ---- load B tile into Bs[k][n] ----
        if (TRANS_B) {
            // B is [N,K]; tile rows n0..n0+63, cols k0..k0+31
            #pragma unroll
            for (int i = 0; i < 4; i++) {
                int id = tid + i * 128;
                int n  = id >> 3;             // 0..63
                int kv = id & 7;              // 0..7
                float4 vb = *(const float4*)(B + (long long)(n0 + n) * K + k0 + kv * 4);
                Bs[kv * 4 + 0][n] = vb.x;
                Bs[kv * 4 + 1][n] = vb.y;
                Bs[kv * 4 + 2][n] = vb.z;
                Bs[kv * 4 + 3][n] = vb.w;
            }
        } else {
            // B is [K,N]; tile rows k0..k0+31, cols n0..n0+63
            #pragma unroll
            for (int i = 0; i < 4; i++) {
                int id = tid + i * 128;
                int kk = id >> 4;             // 0..31
                int nv = id & 15;             // 0..15
                float4 vb = *(const float4*)(B + (long long)(k0 + kk) * N + n0 + nv * 4);
                *(float4*)&Bs[kk][nv * 4] = vb;
            }
        }
        __syncthreads();

        // ---- compute ----
        #pragma unroll
        for (int kk = 0; kk < BK; kk++) {
            float a[8], b[4];
            #pragma unroll
            for (int i = 0; i < 8; i++) a[i] = As[kk][ty * 8 + i];
            #pragma unroll
            for (int j = 0; j < 4; j++) b[j] = Bs[kk][tx * 4 + j];
            #pragma unroll
            for (int i = 0; i < 8; i++)
                #pragma unroll
                for (int j = 0; j < 4; j++)
                    acc[i][j] += a[i] * b[j];
        }
        __syncthreads();
    }

    // ---- epilogue ----
    float bj[4] = {0.f, 0.f, 0.f, 0.f};
    if (BIAS) {
        #pragma unroll
        for (int j = 0; j < 4; j++) bj[j] = bias[n0 + tx * 4 + j];
    }
    #pragma unroll
    for (int i = 0; i < 8; i++) {
        int m = m0 + ty * 8 + i;
        float4 vv;
        vv.x = acc[i][0] * alpha + bj[0];
        vv.y = acc[i][1] * alpha + bj[1];
        vv.z = acc[i][2] * alpha + bj[2];
        vv.w = acc[i][3] * alpha + bj[3];
        *(float4*)(C + (long long)m * N + n0 + tx * 4) = vv;
    }
}

// ----------------------------------------------------------------------------
// Block reductions (256 threads)
// ----------------------------------------------------------------------------
__device__ __forceinline__ float blk_reduce(float v, bool is_max)
{
    __shared__ float sh[256];
    int t = threadIdx.x;
    sh[t] = v;
    __syncthreads();
    #pragma unroll
    for (int s = 128; s > 0; s >>= 1) {
        if (t < s) sh[t] = is_max ? fmaxf(sh[t], sh[t + s]) : (sh[t] + sh[t + s]);
        __syncthreads();
    }
    float r = sh[0];
    __syncthreads();
    return r;
}

// ----------------------------------------------------------------------------
// Masked softmax over rows of S [B*Nq, Nk]. Mask dtype chosen by *mtype.
// NIT = Nk/256 (4 or 8). Row data held in registers between passes.
// ----------------------------------------------------------------------------
template<int NIT>
__global__ __launch_bounds__(256)
void softmax_mask_kernel(float* __restrict__ S, const void* __restrict__ mask,
                         const int* __restrict__ mtype_ptr, int Nk)
{
    const long long row = blockIdx.x;
    float* s = S + row * (long long)Nk;
    const long long mbase = row * (long long)Nk;
    const int t = threadIdx.x;
    const int mtype = *mtype_ptr;   // uniform across grid

    float e[NIT];
    float mx = -INFINITY;
    #pragma unroll
    for (int i = 0; i < NIT; i++) {
        int idx = t + i * 256;
        float v = s[idx];
        bool masked;
        if (mtype == 0)      masked = ((const int*)    mask)[mbase + idx] != 0;
        else if (mtype == 1) masked = ((const uint8_t*)mask)[mbase + idx] != 0;
        else                 masked = ((const float*)  mask)[mbase + idx] != 0.f;
        e[i] = masked ? -INFINITY : v;
        mx = fmaxf(mx, e[i]);
    }
    mx = blk_reduce(mx, true);

    float sum = 0.f;
    #pragma unroll
    for (int i = 0; i < NIT; i++) {
        float ev = (e[i] == -INFINITY) ? 0.f : __expf(e[i] - mx);
        e[i] = ev;
        sum += ev;
    }
    sum = blk_reduce(sum, false);
    float inv = (sum > 0.f) ? (1.f / sum) : 0.f;

    #pragma unroll
    for (int i = 0; i < NIT; i++)
        s[t + i * 256] = e[i] * inv;
}

// ----------------------------------------------------------------------------
// LayerNorm(H=256) * gamma + beta + residual. One block (256 thr) per row.
// ----------------------------------------------------------------------------
__global__ __launch_bounds__(256)
void ln_res_kernel(const float* __restrict__ x, const float* __restrict__ res,
                   const float* __restrict__ gamma, const float* __restrict__ beta,
                   float* __restrict__ out)
{
    const long long row = blockIdx.x;
    const int t = threadIdx.x;
    float v = x[row * HDIM + t];
    float mu = blk_reduce(v, false) * (1.f / HDIM);
    float d = v - mu;
    float var = blk_reduce(d * d, false) * (1.f / HDIM);
    float ln = d * rsqrtf(var + 1e-5f) * gamma[t] + beta[t];
    out[row * HDIM + t] = ln + res[row * HDIM + t];
}

__global__ void add_kernel(const float* __restrict__ a, const float* __restrict__ b,
                           float* __restrict__ o, long long n)
{
    long long i = (long long)blockIdx.x * blockDim.x + threadIdx.x;
    if (i < n) o[i] = a[i] + b[i];
}

// ----------------------------------------------------------------------------
// Host orchestration
// ----------------------------------------------------------------------------
static void proj3(const float* x, int M, const float* W, const float* b,
                  float* outp, float* t0, float* t1)
{
    // 3 chained [M,256] @ [256,256] + bias
    dim3 g(HDIM / 64, M / 64, 1);
    sgemm_kernel<false, true><<<g, 128>>>(x,  W + 0 * 65536, b + 0 * 256, t0,
                                          M, HDIM, HDIM, 0, 0, 0, 1.f);
    sgemm_kernel<false, true><<<g, 128>>>(t0, W + 1 * 65536, b + 1 * 256, t1,
                                          M, HDIM, HDIM, 0, 0, 0, 1.f);
    sgemm_kernel<false, true><<<g, 128>>>(t1, W + 2 * 65536, b + 2 * 256, outp,
                                          M, HDIM, HDIM, 0, 0, 0, 1.f);
}

static void run_layer(const float* x1, const float* x2, const void* mask,
                      const int* mtype_ptr, int Nk,
                      const float* Wq_l, const float* bq_l,
                      const float* Wk_l, const float* bk_l,
                      const float* Wv_l, const float* bv_l,
                      const float* gamma_l, const float* beta_l,
                      float* xout,
                      float* t0, float* t1, float* q, float* k, float* v,
                      float* s, float* attn)
{
    const int Bb = 16, Nq = 1024;
    const int Mq = Bb * Nq;
    const int Mk = Bb * Nk;

    proj3(x1, Mq, Wq_l, bq_l, q, t0, t1);
    proj3(x2, Mk, Wk_l, bk_l, k, t0, t1);
    proj3(x2, Mk, Wv_l, bv_l, v, t0, t1);

    // scores: S[b] = Q[b] @ K[b]^T * (1/16)
    {
        dim3 g(Nk / 64, Nq / 64, Bb);
        sgemm_kernel<true, false><<<g, 128>>>(q, k, nullptr, s,
            Nq, Nk, HDIM,
            (long long)Nq * HDIM, (long long)Nk * HDIM, (long long)Nq * Nk,
            0.0625f);
    }

    // masked softmax
    if (Nk == 1024) softmax_mask_kernel<4><<<Bb * Nq, 256>>>(s, mask, mtype_ptr, Nk);
    else            softmax_mask_kernel<8><<<Bb * Nq, 256>>>(s, mask, mtype_ptr, Nk);

    // attn out: X[b] = S[b] @ V[b]
    {
        dim3 g(HDIM / 64, Nq / 64, Bb);
        sgemm_kernel<false, false><<<g, 128>>>(s, v, nullptr, attn,
            Nq, HDIM, Nk,
            (long long)Nq * Nk, (long long)Nk * HDIM, (long long)Nq * HDIM,
            1.0f);
    }

    // LN + residual
    ln_res_kernel<<<Bb * Nq, 256>>>(attn, x1, gamma_l, beta_l, xout);
}

extern "C" void kernel_launch(void* const* d_in, const int* in_sizes, int n_in,
                              void* d_out, int out_size)
{
    const float* future  = (const float*)d_in[0];
    const float* history = (const float*)d_in[1];
    const float* graph   = (const float*)d_in[2];
    const void*  mask_hf = d_in[3];
    const void*  mask_fg = d_in[4];
    const float* Wq      = (const float*)d_in[5];
    const float* bq      = (const float*)d_in[6];
    const float* Wk      = (const float*)d_in[7];
    const float* bk      = (const float*)d_in[8];
    const float* Wv      = (const float*)d_in[9];
    const float* bv      = (const float*)d_in[10];
    const float* gamma   = (const float*)d_in[11];
    const float* beta    = (const float*)d_in[12];
    float* out = (float*)d_out;

    float *t0, *t1, *q, *k, *v, *s, *attn, *xA, *xB;
    int *mt_hf, *mt_fg;
    cudaGetSymbolAddress((void**)&t0,    g_t0);
    cudaGetSymbolAddress((void**)&t1,    g_t1);
    cudaGetSymbolAddress((void**)&q,     g_q);
    cudaGetSymbolAddress((void**)&k,     g_k);
    cudaGetSymbolAddress((void**)&v,     g_v);
    cudaGetSymbolAddress((void**)&s,     g_s);
    cudaGetSymbolAddress((void**)&attn,  g_attn);
    cudaGetSymbolAddress((void**)&xA,    g_xA);
    cudaGetSymbolAddress((void**)&xB,    g_xB);
    cudaGetSymbolAddress((void**)&mt_hf, g_mtype_hf);
    cudaGetSymbolAddress((void**)&mt_fg, g_mtype_fg);

    // Detect mask dtypes (safe word count: n_elems/4 words valid in all encodings)
    {
        int nw_hf = in_sizes[3] / 4; if (nw_hf > 65536) nw_hf = 65536;
        int nw_fg = in_sizes[4] / 4; if (nw_fg > 65536) nw_fg = 65536;
        detect_mask_kernel<<<1, 256>>>((const uint32_t*)mask_hf, nw_hf, mt_hf);
        detect_mask_kernel<<<1, 256>>>((const uint32_t*)mask_fg, nw_fg, mt_fg);
    }

    const long long WL = 3LL * 65536;   // weight stride per layer
    const long long BL = 3LL * 256;     // bias stride per layer

    // encoder 1: cross(x, history), layers 0..1
    run_layer(future, history, mask_hf, mt_hf, 1024,
              Wq + 0 * WL, bq + 0 * BL, Wk + 0 * WL, bk + 0 * BL, Wv + 0 * WL, bv + 0 * BL,
              gamma + 0 * 256, beta + 0 * 256,
              xA, t0, t1, q, k, v, s, attn);
    run_layer(xA, history, mask_hf, mt_hf, 1024,
              Wq + 1 * WL, bq + 1 * BL, Wk + 1 * WL, bk + 1 * BL, Wv + 1 * WL, bv + 1 * BL,
              gamma + 1 * 256, beta + 1 * 256,
              xB, t0, t1, q, k, v, s, attn);
    // encoder 2: cross(x, graph), layers 2..3
    run_layer(xB, graph, mask_fg, mt_fg, 2048,
              Wq + 2 * WL, bq + 2 * BL, Wk + 2 * WL, bk + 2 * BL, Wv + 2 * WL, bv + 2 * BL,
              gamma + 2 * 256, beta + 2 * 256,
              xA, t0, t1, q, k, v, s, attn);
    run_layer(xA, graph, mask_fg, mt_fg, 2048,
              Wq + 3 * WL, bq + 3 * BL, Wk + 3 * WL, bk + 3 * BL, Wv + 3 * WL, bv + 3 * BL,
              gamma + 3 * 256, beta + 3 * 256,
              xB, t0, t1, q, k, v, s, attn);

    // out = future + x
    long long n = (long long)out_size;
    add_kernel<<<(unsigned)((n + 255) / 256), 256>>>(future, xB, out, n);
}